// round 6
// baseline (speedup 1.0000x reference)
#include <cuda_runtime.h>
#include <math.h>
#include <float.h>

#define BB    2
#define NPTS  8192
#define KNN   16
#define KP1   17
#define C1    16
#define CC    64
#define ROWS1 (BB*NPTS*KNN)   /* 262144 edge rows */
#define ROWS2 (BB*NPTS)       /* 16384 point rows */
#define FULLW 0xffffffffu
#define IMAXS 0x7fffffff

// ---------------- scratch ----------------
__device__ float4 g_p4[ROWS2];                      // packed (x,y,z,|p|^2)
__device__ int    g_nbr[ROWS2*KP1];                 // sorted knn indices (incl. self at 0)
__device__ float  g_pool[(size_t)CC*ROWS2];         // [c][bn]  pooled (post relu)
__device__ float  g_y2 [(size_t)CC*ROWS2];          // [c][bn]  pre-BN point branch
__device__ float  g_y3 [(size_t)CC*ROWS2];          // [c][bn]  pre-BN final
__device__ float  g_acc[512];                       // per-group sums: base g*128 (+64 = sumsq)
__device__ float  g_mr [512];                       // per-group folded scale(+0)/shift(+64)

// ---------------- helpers ----------------
__global__ void k_zero() { g_acc[threadIdx.x] = 0.0f; }

__global__ void k_prep(const float* __restrict__ pts) {
    int i = blockIdx.x*blockDim.x + threadIdx.x;
    if (i < ROWS2) {
        float x = pts[3*i], y = pts[3*i+1], z = pts[3*i+2];
        g_p4[i] = make_float4(x, y, z, x*x + y*y + z*z);
    }
}

__device__ __forceinline__ bool lexless(float d0, int i0, float d1, int i1) {
    return d0 < d1 || (d0 == d1 && i0 < i1);
}

// warp-distributed top-17 insert (list ascending by lane; lanes>=17 hold +inf)
__device__ __forceinline__ void insert_warp(unsigned mask, float d, int j,
        float& ld, int& li, float& thrd, int& thri, int lane) {
    while (mask) {
        int s = __ffs(mask) - 1;
        mask &= mask - 1;
        float dc = __shfl_sync(FULLW, d, s);
        int   jc = __shfl_sync(FULLW, j, s);
        if (lexless(dc, jc, thrd, thri)) {       // warp-uniform recheck
            unsigned lessm = __ballot_sync(FULLW, lexless(ld, li, dc, jc));
            int pos = __popc(lessm);
            float pd = __shfl_up_sync(FULLW, ld, 1);
            int   pi = __shfl_up_sync(FULLW, li, 1);
            if (lane > pos)       { ld = pd; li = pi; }
            else if (lane == pos) { ld = dc; li = jc; }
            thrd = __shfl_sync(FULLW, ld, KP1-1);
            thri = __shfl_sync(FULLW, li, KP1-1);
        }
    }
}

// warp-per-2-queries brute-force top-17; candidate load shared between queries.
__global__ void __launch_bounds__(1024, 1) k_knn() {
    extern __shared__ float4 sp[];
    const int tid = threadIdx.x;
    const int blocksPerBatch = NPTS/64;             // 64 queries per block
    const int b = blockIdx.x / blocksPerBatch;
    const int qbase = (blockIdx.x % blocksPerBatch) * 64;

    for (int i = tid; i < NPTS; i += 1024) sp[i] = g_p4[b*NPTS + i];
    __syncthreads();

    const int w = tid >> 5, lane = tid & 31;
    const int q0 = qbase + 2*w, q1 = q0 + 1;
    const float4 qa = sp[q0], qb = sp[q1];

    float ld0 = FLT_MAX, ld1 = FLT_MAX;  int li0 = IMAXS, li1 = IMAXS;
    float t0d = FLT_MAX, t1d = FLT_MAX;  int t0i = IMAXS, t1i = IMAXS;

    for (int j = lane; j < NPTS; j += 32) {
        float4 p = sp[j];
        float d0 = (qa.w + p.w) - 2.0f*(qa.x*p.x + qa.y*p.y + qa.z*p.z);
        float d1 = (qb.w + p.w) - 2.0f*(qb.x*p.x + qb.y*p.y + qb.z*p.z);
        unsigned m0 = __ballot_sync(FULLW, lexless(d0, j, t0d, t0i));
        if (m0) insert_warp(m0, d0, j, ld0, li0, t0d, t0i, lane);
        unsigned m1 = __ballot_sync(FULLW, lexless(d1, j, t1d, t1i));
        if (m1) insert_warp(m1, d1, j, ld1, li1, t1d, t1i, lane);
    }

    if (lane < KP1) {
        g_nbr[(b*NPTS + q0)*KP1 + lane] = li0;
        g_nbr[(b*NPTS + q1)*KP1 + lane] = li1;
    }
}

// shared edge-feature builder (recomputed in 3 kernels; g_nbr/g_p4 are L1/L2-hot)
__device__ __forceinline__ void edge_feat(int bn, int k, float* f) {
    int b = bn >> 13;
    int i0 = g_nbr[bn*KP1];
    int in = g_nbr[bn*KP1 + 1 + k];
    float4 p0 = g_p4[b*NPTS + i0];
    float4 pn = g_p4[b*NPTS + in];
    f[0] = p0.x; f[1] = p0.y; f[2] = p0.z;
    float rx = pn.x - p0.x, ry = pn.y - p0.y, rz = pn.z - p0.z;
    f[3] = rx; f[4] = ry; f[5] = rz;
    f[6] = sqrtf(rx*rx + ry*ry + rz*rz + 1e-8f);
}

// layer-1a pre-BN stats only (no store)
__global__ void __launch_bounds__(256) k_s1a(const float* __restrict__ W1a) {
    __shared__ float sw[C1*7];
    int t = threadIdx.x;
    if (t < C1*7) sw[t] = W1a[t];
    __syncthreads();
    float sum[C1], sq[C1];
    #pragma unroll
    for (int c = 0; c < C1; ++c) { sum[c] = 0.0f; sq[c] = 0.0f; }
    for (int row = blockIdx.x*256 + t; row < ROWS1; row += gridDim.x*256) {
        float f[7]; edge_feat(row >> 4, row & 15, f);
        #pragma unroll
        for (int c = 0; c < C1; ++c) {
            float a = 0.0f;
            #pragma unroll
            for (int j = 0; j < 7; ++j) a += f[j]*sw[c*7 + j];
            sum[c] += a; sq[c] += a*a;
        }
    }
    #pragma unroll
    for (int off = 16; off; off >>= 1) {
        #pragma unroll
        for (int c = 0; c < C1; ++c) {
            sum[c] += __shfl_xor_sync(FULLW, sum[c], off);
            sq[c]  += __shfl_xor_sync(FULLW, sq[c],  off);
        }
    }
    if ((t & 31) == 0) {
        #pragma unroll
        for (int c = 0; c < C1; ++c) {
            atomicAdd(&g_acc[c], sum[c]);
            atomicAdd(&g_acc[64 + c], sq[c]);
        }
    }
}

// fold BN into scale/shift:  y_bn = y*scale + shift
__global__ void k_fin(int base, float inv_cnt, int nch,
                      const float* __restrict__ gamma, const float* __restrict__ beta) {
    int c = threadIdx.x;
    if (c < nch) {
        float mean = g_acc[base + c]*inv_cnt;
        float var  = g_acc[base + 64 + c]*inv_cnt - mean*mean;
        float r = rsqrtf(var + 1e-5f);
        float sc = r*gamma[c];
        g_mr[base + c]      = sc;
        g_mr[base + 64 + c] = beta[c] - mean*sc;
    }
}

// layer-1b stats only (recompute 1a, BN+relu, 16x{32-half} matmul). blockIdx.y = half.
__global__ void __launch_bounds__(256) k_s1b(const float* __restrict__ W1a,
                                             const float* __restrict__ W1b) {
    __shared__ float sa[C1*7];
    __shared__ float wt[C1*32];    // half of W1b, transposed: wt[j*32+cl]
    __shared__ float s1[C1*2];
    int t = threadIdx.x;
    int cbase = blockIdx.y * 32;
    if (t < C1*7) sa[t] = W1a[t];
    if (t < C1) { s1[t] = g_mr[t]; s1[16 + t] = g_mr[64 + t]; }
    for (int i = t; i < C1*32; i += 256) {
        int j = i & 15, cl = i >> 4;
        wt[j*32 + cl] = W1b[(cbase + cl)*C1 + j];
    }
    __syncthreads();
    const float4* wtv = (const float4*)wt;
    float sum[32], sq[32];
    #pragma unroll
    for (int c = 0; c < 32; ++c) { sum[c] = 0.0f; sq[c] = 0.0f; }
    for (int row = blockIdx.x*256 + t; row < ROWS1; row += gridDim.x*256) {
        float f[7]; edge_feat(row >> 4, row & 15, f);
        float h[C1];
        #pragma unroll
        for (int c = 0; c < C1; ++c) {
            float a = 0.0f;
            #pragma unroll
            for (int j = 0; j < 7; ++j) a += f[j]*sa[c*7 + j];
            h[c] = fmaxf(a*s1[c] + s1[16 + c], 0.0f);
        }
        float y[32];
        #pragma unroll
        for (int c = 0; c < 32; ++c) y[c] = 0.0f;
        #pragma unroll
        for (int j = 0; j < C1; ++j) {
            float hj = h[j];
            #pragma unroll
            for (int c4 = 0; c4 < 8; ++c4) {
                float4 w4 = wtv[j*8 + c4];
                y[4*c4+0] += hj*w4.x; y[4*c4+1] += hj*w4.y;
                y[4*c4+2] += hj*w4.z; y[4*c4+3] += hj*w4.w;
            }
        }
        #pragma unroll
        for (int c = 0; c < 32; ++c) { sum[c] += y[c]; sq[c] += y[c]*y[c]; }
    }
    #pragma unroll
    for (int off = 16; off; off >>= 1) {
        #pragma unroll
        for (int c = 0; c < 32; ++c) {
            sum[c] += __shfl_xor_sync(FULLW, sum[c], off);
            sq[c]  += __shfl_xor_sync(FULLW, sq[c],  off);
        }
    }
    if ((t & 31) == 0) {
        #pragma unroll
        for (int c = 0; c < 32; ++c) {
            atomicAdd(&g_acc[128 + cbase + c], sum[c]);
            atomicAdd(&g_acc[128 + 64 + cbase + c], sq[c]);
        }
    }
}

// recompute 1a+1b with both BNs folded, relu, max over K=16 -> g_pool (channel-major)
__global__ void __launch_bounds__(256) k_pool2(const float* __restrict__ W1a,
                                               const float* __restrict__ W1b) {
    __shared__ float sa[C1*7];
    __shared__ float wt[C1*CC];    // wt[j*64+c]
    __shared__ float s1[C1*2];
    __shared__ float s2[CC*2];
    __shared__ float spool[CC*16];
    int t = threadIdx.x;
    if (t < C1*7) sa[t] = W1a[t];
    if (t < C1) { s1[t] = g_mr[t]; s1[16 + t] = g_mr[64 + t]; }
    if (t < CC) { s2[t] = g_mr[128 + t]; s2[64 + t] = g_mr[128 + 64 + t]; }
    for (int i = t; i < C1*CC; i += 256) {
        int c = i >> 4, j = i & 15;
        wt[j*CC + c] = W1b[i];
    }
    __syncthreads();
    const float4* wtv = (const float4*)wt;
    int lane = t & 31, w = t >> 5;
    int grp = lane >> 4, kl = lane & 15;
    int bn = blockIdx.x*16 + w*2 + grp;

    float f[7]; edge_feat(bn, kl, f);
    float h[C1];
    #pragma unroll
    for (int c = 0; c < C1; ++c) {
        float a = 0.0f;
        #pragma unroll
        for (int j = 0; j < 7; ++j) a += f[j]*sa[c*7 + j];
        h[c] = fmaxf(a*s1[c] + s1[16 + c], 0.0f);
    }
    float y[CC];
    #pragma unroll
    for (int c = 0; c < CC; ++c) y[c] = 0.0f;
    #pragma unroll
    for (int j = 0; j < C1; ++j) {
        float hj = h[j];
        #pragma unroll
        for (int c4 = 0; c4 < 16; ++c4) {
            float4 w4 = wtv[j*16 + c4];
            y[4*c4+0] += hj*w4.x; y[4*c4+1] += hj*w4.y;
            y[4*c4+2] += hj*w4.z; y[4*c4+3] += hj*w4.w;
        }
    }
    #pragma unroll
    for (int c = 0; c < CC; ++c)
        y[c] = fmaxf(y[c]*s2[c] + s2[64 + c], 0.0f);
    // max over the 16 neighbor lanes of this group
    #pragma unroll
    for (int off = 1; off < 16; off <<= 1) {
        #pragma unroll
        for (int c = 0; c < CC; ++c)
            y[c] = fmaxf(y[c], __shfl_xor_sync(FULLW, y[c], off));
    }
    if (kl == 0) {
        int pt = w*2 + grp;
        #pragma unroll
        for (int c = 0; c < CC; ++c) spool[c*16 + pt] = y[c];
    }
    __syncthreads();
    for (int e = t; e < CC*16; e += 256) {
        int c = e >> 4, pl = e & 15;
        g_pool[(size_t)c*ROWS2 + blockIdx.x*16 + pl] = spool[e];
    }
}

// per-channel sum/sumsq over channel-major [c][rows] (kept for small y2/y3)
__global__ void k_colsum(const float* __restrict__ src, int rows, int accBase) {
    int c = blockIdx.x;
    int per = rows / gridDim.y;
    int start = blockIdx.y * per;
    const float* p = src + (size_t)c*rows;
    float s = 0.0f, s2 = 0.0f;
    for (int i = start + threadIdx.x; i < start + per; i += blockDim.x) {
        float v = p[i]; s += v; s2 += v*v;
    }
    #pragma unroll
    for (int off = 16; off; off >>= 1) {
        s  += __shfl_xor_sync(FULLW, s,  off);
        s2 += __shfl_xor_sync(FULLW, s2, off);
    }
    __shared__ float ss[8], sqm[8];
    int w = threadIdx.x >> 5, lane = threadIdx.x & 31;
    if (lane == 0) { ss[w] = s; sqm[w] = s2; }
    __syncthreads();
    if (threadIdx.x == 0) {
        float a = 0.0f, a2 = 0.0f;
        for (int i = 0; i < (int)blockDim.x/32; ++i) { a += ss[i]; a2 += sqm[i]; }
        atomicAdd(&g_acc[accBase + c], a);
        atomicAdd(&g_acc[accBase + 64 + c], a2);
    }
}

// point branch 3 -> 64 (pre-BN)
__global__ void k_pts(const float* __restrict__ W2) {
    __shared__ float sw[CC*3];
    int t = threadIdx.x;
    if (t < CC*3) sw[t] = W2[t];
    __syncthreads();
    int bn = blockIdx.x*blockDim.x + t;
    float4 p = g_p4[bn];
    #pragma unroll
    for (int c = 0; c < CC; ++c) {
        float a = p.x*sw[c*3] + p.y*sw[c*3+1] + p.z*sw[c*3+2];
        g_y2[(size_t)c*ROWS2 + bn] = a;
    }
}

// concat(bn+relu(y2), pool) -> 128x64 matmul, pre-BN channel-major
__global__ void k_l3(const float* __restrict__ W3) {
    extern __shared__ float smem[];
    float* sw  = smem;               // [128][65] -> sw[j*65+c]
    float* sin = smem + 128*65;      // [128][32] -> sin[j*32+bnl]
    int t = threadIdx.x;             // 256
    for (int i = t; i < 64*128; i += 256) {
        int c = i >> 7, j = i & 127;
        sw[j*65 + c] = W3[i];
    }
    int bn0 = blockIdx.x * 32;
    for (int e = t; e < 128*32; e += 256) {
        int j = e >> 5, bnl = e & 31;
        float v;
        if (j < 64) {
            v = g_y2[(size_t)j*ROWS2 + bn0 + bnl];
            v = fmaxf(v*g_mr[256 + j] + g_mr[256 + 64 + j], 0.0f);
        } else {
            v = g_pool[(size_t)(j - 64)*ROWS2 + bn0 + bnl];
        }
        sin[e] = v;
    }
    __syncthreads();
    int tx = t & 31, ty = t >> 5;
    float acc[8];
    #pragma unroll
    for (int i = 0; i < 8; ++i) acc[i] = 0.0f;
    for (int j = 0; j < 128; ++j) {
        float x = sin[j*32 + tx];
        #pragma unroll
        for (int i = 0; i < 8; ++i) acc[i] += x*sw[j*65 + ty*8 + i];
    }
    #pragma unroll
    for (int i = 0; i < 8; ++i)
        g_y3[(size_t)(ty*8 + i)*ROWS2 + bn0 + tx] = acc[i];
}

// bn+relu(final) + transpose to row-major output (B,N,64)
__global__ void k_out(float* __restrict__ out) {
    __shared__ float s[64*33];
    int t = threadIdx.x;
    int bn0 = blockIdx.x*32;
    for (int e = t; e < 2048; e += 256) {
        int c = e >> 5, bnl = e & 31;
        float v = g_y3[(size_t)c*ROWS2 + bn0 + bnl];
        v = fmaxf(v*g_mr[384 + c] + g_mr[384 + 64 + c], 0.0f);
        s[c*33 + bnl] = v;
    }
    __syncthreads();
    for (int e = t; e < 2048; e += 256) {
        int bnl = e >> 6, c = e & 63;
        out[(size_t)(bn0 + bnl)*64 + c] = s[c*33 + bnl];
    }
}

// ---------------- launch ----------------
extern "C" void kernel_launch(void* const* d_in, const int* in_sizes, int n_in,
                              void* d_out, int out_size) {
    const float* pts = (const float*)d_in[0];
    const float* W1a = (const float*)d_in[1];
    const float* g1a = (const float*)d_in[2];
    const float* b1a = (const float*)d_in[3];
    const float* W1b = (const float*)d_in[4];
    const float* g1b = (const float*)d_in[5];
    const float* b1b = (const float*)d_in[6];
    const float* W2  = (const float*)d_in[7];
    const float* g2  = (const float*)d_in[8];
    const float* b2  = (const float*)d_in[9];
    const float* W3  = (const float*)d_in[10];
    const float* g3  = (const float*)d_in[11];
    const float* b3  = (const float*)d_in[12];
    float* out = (float*)d_out;

    (void)in_sizes; (void)n_in; (void)out_size;

    cudaFuncSetAttribute(k_knn, cudaFuncAttributeMaxDynamicSharedMemorySize,
                         NPTS*(int)sizeof(float4));
    cudaFuncSetAttribute(k_l3, cudaFuncAttributeMaxDynamicSharedMemorySize,
                         (128*65 + 128*32)*(int)sizeof(float));

    float *py2, *py3;
    cudaGetSymbolAddress((void**)&py2, g_y2);
    cudaGetSymbolAddress((void**)&py3, g_y3);

    k_zero<<<1, 512>>>();
    k_prep<<<(ROWS2 + 255)/256, 256>>>(pts);
    k_knn<<<BB*(NPTS/64), 1024, NPTS*(int)sizeof(float4)>>>();

    k_s1a<<<296, 256>>>(W1a);
    k_fin<<<1, 64>>>(0, 1.0f/(float)ROWS1, 16, g1a, b1a);

    k_s1b<<<dim3(296, 2), 256>>>(W1a, W1b);
    k_fin<<<1, 64>>>(128, 1.0f/(float)ROWS1, 64, g1b, b1b);

    k_pts<<<ROWS2/256, 256>>>(W2);
    k_colsum<<<dim3(64, 4), 256>>>(py2, ROWS2, 256);
    k_fin<<<1, 64>>>(256, 1.0f/(float)ROWS2, 64, g2, b2);

    k_pool2<<<ROWS2/16, 256>>>(W1a, W1b);

    k_l3<<<ROWS2/32, 256, (128*65 + 128*32)*(int)sizeof(float)>>>(W3);
    k_colsum<<<dim3(64, 4), 256>>>(py3, ROWS2, 384);
    k_fin<<<1, 64>>>(384, 1.0f/(float)ROWS2, 64, g3, b3);

    k_out<<<ROWS2/32, 256>>>(out);
}

// round 7
// speedup vs baseline: 2.5015x; 2.5015x over previous
#include <cuda_runtime.h>
#include <math.h>
#include <float.h>

#define BB    2
#define NPTS  8192
#define KNN   16
#define KP1   17
#define C1    16
#define CC    64
#define ROWS1 (BB*NPTS*KNN)   /* 262144 edge rows */
#define ROWS2 (BB*NPTS)       /* 16384 point rows */
#define FULLW 0xffffffffu
#define IMAXS 0x7fffffff

// ---------------- scratch (static device globals; no runtime allocs) ----------------
__device__ float4 g_p4[ROWS2];                      // packed (x,y,z,|p|^2)
__device__ int    g_nbr[ROWS2*KP1];                 // sorted knn indices (incl. self at 0)
__device__ float  g_y1a[(size_t)C1*ROWS1];          // [c][row] pre-BN layer1a
__device__ float  g_y1b[(size_t)CC*ROWS1];          // [c][row] pre-BN layer1b
__device__ float  g_pool[(size_t)CC*ROWS2];         // [c][bn]  pooled (post relu)
__device__ float  g_y2 [(size_t)CC*ROWS2];          // [c][bn]  pre-BN point branch
__device__ float  g_y3 [(size_t)CC*ROWS2];          // [c][bn]  pre-BN final
__device__ float  g_acc[512];                       // per-group sums: base g*128 (+64 = sumsq)
__device__ float  g_mr [512];                       // per-group folded scale(+0)/shift(+64)

// ---------------- kernels ----------------
__global__ void k_zero() { g_acc[threadIdx.x] = 0.0f; }

__global__ void k_prep(const float* __restrict__ pts) {
    int i = blockIdx.x*blockDim.x + threadIdx.x;
    if (i < ROWS2) {
        float x = pts[3*i], y = pts[3*i+1], z = pts[3*i+2];
        g_p4[i] = make_float4(x, y, z, x*x + y*y + z*z);
    }
}

__device__ __forceinline__ bool lexless(float d0, int i0, float d1, int i1) {
    return d0 < d1 || (d0 == d1 && i0 < i1);
}

// warp-distributed top-17 insert (list ascending by lane; lanes>=17 hold +inf)
__device__ __forceinline__ void insert_warp(unsigned mask, float d, int j,
        float& ld, int& li, float& thrd, int& thri, int lane) {
    while (mask) {
        int s = __ffs(mask) - 1;
        mask &= mask - 1;
        float dc = __shfl_sync(FULLW, d, s);
        int   jc = __shfl_sync(FULLW, j, s);
        if (lexless(dc, jc, thrd, thri)) {       // warp-uniform recheck
            unsigned lessm = __ballot_sync(FULLW, lexless(ld, li, dc, jc));
            int pos = __popc(lessm);
            float pd = __shfl_up_sync(FULLW, ld, 1);
            int   pi = __shfl_up_sync(FULLW, li, 1);
            if (lane > pos)       { ld = pd; li = pi; }
            else if (lane == pos) { ld = dc; li = jc; }
            thrd = __shfl_sync(FULLW, ld, KP1-1);
            thri = __shfl_sync(FULLW, li, KP1-1);
        }
    }
}

// warp-per-2-queries brute-force top-17; candidate load shared between queries.
// Lexicographic (d2, idx) ordering matches jax top_k tie rules; indices unique.
__global__ void __launch_bounds__(1024, 1) k_knn() {
    extern __shared__ float4 sp[];
    const int tid = threadIdx.x;
    const int blocksPerBatch = NPTS/64;             // 64 queries per block
    const int b = blockIdx.x / blocksPerBatch;
    const int qbase = (blockIdx.x % blocksPerBatch) * 64;

    for (int i = tid; i < NPTS; i += 1024) sp[i] = g_p4[b*NPTS + i];
    __syncthreads();

    const int w = tid >> 5, lane = tid & 31;
    const int q0 = qbase + 2*w, q1 = q0 + 1;
    const float4 qa = sp[q0], qb = sp[q1];

    float ld0 = FLT_MAX, ld1 = FLT_MAX;  int li0 = IMAXS, li1 = IMAXS;
    float t0d = FLT_MAX, t1d = FLT_MAX;  int t0i = IMAXS, t1i = IMAXS;

    for (int j = lane; j < NPTS; j += 32) {
        float4 p = sp[j];
        float d0 = (qa.w + p.w) - 2.0f*(qa.x*p.x + qa.y*p.y + qa.z*p.z);
        float d1 = (qb.w + p.w) - 2.0f*(qb.x*p.x + qb.y*p.y + qb.z*p.z);
        unsigned m0 = __ballot_sync(FULLW, lexless(d0, j, t0d, t0i));
        if (m0) insert_warp(m0, d0, j, ld0, li0, t0d, t0i, lane);
        unsigned m1 = __ballot_sync(FULLW, lexless(d1, j, t1d, t1i));
        if (m1) insert_warp(m1, d1, j, ld1, li1, t1d, t1i, lane);
    }

    if (lane < KP1) {
        g_nbr[(b*NPTS + q0)*KP1 + lane] = li0;
        g_nbr[(b*NPTS + q1)*KP1 + lane] = li1;
    }
}

// edge features (7) -> 16, store pre-BN channel-major
__global__ void k_l1a(const float* __restrict__ W1a) {
    __shared__ float sw[C1*7];
    int t = threadIdx.x;
    if (t < C1*7) sw[t] = W1a[t];
    __syncthreads();
    int row = blockIdx.x*blockDim.x + t;
    int bn = row >> 4, k = row & 15;
    int b = bn >> 13;
    int i0 = g_nbr[bn*KP1];
    int in = g_nbr[bn*KP1 + 1 + k];
    float4 p0 = g_p4[b*NPTS + i0];
    float4 pn = g_p4[b*NPTS + in];
    float f[7];
    f[0] = p0.x; f[1] = p0.y; f[2] = p0.z;
    float rx = pn.x - p0.x, ry = pn.y - p0.y, rz = pn.z - p0.z;
    f[3] = rx; f[4] = ry; f[5] = rz;
    f[6] = sqrtf(rx*rx + ry*ry + rz*rz + 1e-8f);
    #pragma unroll
    for (int c = 0; c < C1; ++c) {
        float a = 0.0f;
        #pragma unroll
        for (int j = 0; j < 7; ++j) a += f[j]*sw[c*7 + j];
        g_y1a[(size_t)c*ROWS1 + row] = a;
    }
}

// per-channel sum/sumsq over channel-major [c][rows]
__global__ void k_colsum(const float* __restrict__ src, int rows, int accBase) {
    int c = blockIdx.x;
    int per = rows / gridDim.y;
    int start = blockIdx.y * per;
    const float* p = src + (size_t)c*rows;
    float s = 0.0f, s2 = 0.0f;
    for (int i = start + threadIdx.x; i < start + per; i += blockDim.x) {
        float v = p[i]; s += v; s2 += v*v;
    }
    #pragma unroll
    for (int off = 16; off; off >>= 1) {
        s  += __shfl_xor_sync(FULLW, s,  off);
        s2 += __shfl_xor_sync(FULLW, s2, off);
    }
    __shared__ float ss[8], sq[8];
    int w = threadIdx.x >> 5, lane = threadIdx.x & 31;
    if (lane == 0) { ss[w] = s; sq[w] = s2; }
    __syncthreads();
    if (threadIdx.x == 0) {
        float a = 0.0f, a2 = 0.0f;
        for (int i = 0; i < (int)blockDim.x/32; ++i) { a += ss[i]; a2 += sq[i]; }
        atomicAdd(&g_acc[accBase + c], a);
        atomicAdd(&g_acc[accBase + 64 + c], a2);
    }
}

// fold BN into scale/shift:  y_bn = y*scale + shift
__global__ void k_fin(int base, float inv_cnt, int nch,
                      const float* __restrict__ gamma, const float* __restrict__ beta) {
    int c = threadIdx.x;
    if (c < nch) {
        float mean = g_acc[base + c]*inv_cnt;
        float var  = g_acc[base + 64 + c]*inv_cnt - mean*mean;
        float r = rsqrtf(var + 1e-5f);
        float sc = r*gamma[c];
        g_mr[base + c]      = sc;
        g_mr[base + 64 + c] = beta[c] - mean*sc;
    }
}

// bn+relu(layer1a) -> 16x64 matmul, store pre-BN channel-major
__global__ void k_l1b(const float* __restrict__ W1b) {
    __shared__ float wt[C1*CC];     // wt[j*64+c]
    __shared__ float sc0[C1], sh0[C1];
    int t = threadIdx.x;
    for (int i = t; i < C1*CC; i += blockDim.x) {
        int c = i / C1, j = i % C1;
        wt[j*CC + c] = W1b[i];
    }
    if (t < C1) { sc0[t] = g_mr[t]; sh0[t] = g_mr[64 + t]; }
    __syncthreads();
    int row = blockIdx.x*blockDim.x + t;
    float acc[CC];
    #pragma unroll
    for (int c = 0; c < CC; ++c) acc[c] = 0.0f;
    #pragma unroll
    for (int j = 0; j < C1; ++j) {
        float x = g_y1a[(size_t)j*ROWS1 + row];
        x = fmaxf(x*sc0[j] + sh0[j], 0.0f);
        #pragma unroll
        for (int c = 0; c < CC; ++c) acc[c] += x*wt[j*CC + c];
    }
    #pragma unroll
    for (int c = 0; c < CC; ++c) g_y1b[(size_t)c*ROWS1 + row] = acc[c];
}

// point branch 3 -> 64 (pre-BN)
__global__ void k_pts(const float* __restrict__ W2) {
    __shared__ float sw[CC*3];
    int t = threadIdx.x;
    if (t < CC*3) sw[t] = W2[t];
    __syncthreads();
    int bn = blockIdx.x*blockDim.x + t;
    float4 p = g_p4[bn];
    #pragma unroll
    for (int c = 0; c < CC; ++c) {
        float a = p.x*sw[c*3] + p.y*sw[c*3+1] + p.z*sw[c*3+2];
        g_y2[(size_t)c*ROWS2 + bn] = a;
    }
}

// bn+relu(layer1b) then max over K
__global__ void k_pool() {
    int c = blockIdx.y;
    int bn = blockIdx.x*blockDim.x + threadIdx.x;
    float sc = g_mr[128 + c], sh = g_mr[128 + 64 + c];
    const float4* p = (const float4*)(g_y1b + (size_t)c*ROWS1 + (size_t)bn*KNN);
    float m = -FLT_MAX;
    #pragma unroll
    for (int i = 0; i < 4; ++i) {
        float4 v = p[i];
        m = fmaxf(m, fmaxf(0.0f, v.x*sc + sh));
        m = fmaxf(m, fmaxf(0.0f, v.y*sc + sh));
        m = fmaxf(m, fmaxf(0.0f, v.z*sc + sh));
        m = fmaxf(m, fmaxf(0.0f, v.w*sc + sh));
    }
    g_pool[(size_t)c*ROWS2 + bn] = m;
}

// concat(bn+relu(y2), pool) -> 128x64 matmul, pre-BN channel-major,
// with y3 per-channel sum/sumsq fused (warp holds same 8 channels across 32 points)
__global__ void k_l3(const float* __restrict__ W3) {
    extern __shared__ float smem[];
    float* sw  = smem;               // [128][65] -> sw[j*65+c]
    float* sin = smem + 128*65;      // [128][32] -> sin[j*32+bnl]
    int t = threadIdx.x;             // 256
    for (int i = t; i < 64*128; i += 256) {
        int c = i >> 7, j = i & 127;
        sw[j*65 + c] = W3[i];        // coalesced read of W3
    }
    int bn0 = blockIdx.x * 32;
    for (int e = t; e < 128*32; e += 256) {
        int j = e >> 5, bnl = e & 31;
        float v;
        if (j < 64) {
            v = g_y2[(size_t)j*ROWS2 + bn0 + bnl];
            v = fmaxf(v*g_mr[256 + j] + g_mr[256 + 64 + j], 0.0f);
        } else {
            v = g_pool[(size_t)(j - 64)*ROWS2 + bn0 + bnl];
        }
        sin[e] = v;
    }
    __syncthreads();
    int tx = t & 31, ty = t >> 5;    // ty 0..7 -> 8 channels each; warp == ty
    float acc[8];
    #pragma unroll
    for (int i = 0; i < 8; ++i) acc[i] = 0.0f;
    for (int j = 0; j < 128; ++j) {
        float x = sin[j*32 + tx];
        #pragma unroll
        for (int i = 0; i < 8; ++i) acc[i] += x*sw[j*65 + ty*8 + i];
    }
    #pragma unroll
    for (int i = 0; i < 8; ++i)
        g_y3[(size_t)(ty*8 + i)*ROWS2 + bn0 + tx] = acc[i];
    // fused y3 stats: butterfly over the 32 points held by this warp
    float s[8], q2[8];
    #pragma unroll
    for (int i = 0; i < 8; ++i) { s[i] = acc[i]; q2[i] = acc[i]*acc[i]; }
    #pragma unroll
    for (int off = 16; off; off >>= 1) {
        #pragma unroll
        for (int i = 0; i < 8; ++i) {
            s[i]  += __shfl_xor_sync(FULLW, s[i],  off);
            q2[i] += __shfl_xor_sync(FULLW, q2[i], off);
        }
    }
    if (tx == 0) {
        #pragma unroll
        for (int i = 0; i < 8; ++i) {
            atomicAdd(&g_acc[384 + ty*8 + i], s[i]);
            atomicAdd(&g_acc[384 + 64 + ty*8 + i], q2[i]);
        }
    }
}

// bn+relu(final) + transpose to row-major output (B,N,64)
__global__ void k_out(float* __restrict__ out) {
    __shared__ float s[64*33];
    int t = threadIdx.x;
    int bn0 = blockIdx.x*32;
    for (int e = t; e < 2048; e += 256) {
        int c = e >> 5, bnl = e & 31;
        float v = g_y3[(size_t)c*ROWS2 + bn0 + bnl];
        v = fmaxf(v*g_mr[384 + c] + g_mr[384 + 64 + c], 0.0f);
        s[c*33 + bnl] = v;
    }
    __syncthreads();
    for (int e = t; e < 2048; e += 256) {
        int bnl = e >> 6, c = e & 63;
        out[(size_t)(bn0 + bnl)*64 + c] = s[c*33 + bnl];
    }
}

// ---------------- launch ----------------
extern "C" void kernel_launch(void* const* d_in, const int* in_sizes, int n_in,
                              void* d_out, int out_size) {
    const float* pts = (const float*)d_in[0];
    const float* W1a = (const float*)d_in[1];
    const float* g1a = (const float*)d_in[2];
    const float* b1a = (const float*)d_in[3];
    const float* W1b = (const float*)d_in[4];
    const float* g1b = (const float*)d_in[5];
    const float* b1b = (const float*)d_in[6];
    const float* W2  = (const float*)d_in[7];
    const float* g2  = (const float*)d_in[8];
    const float* b2  = (const float*)d_in[9];
    const float* W3  = (const float*)d_in[10];
    const float* g3  = (const float*)d_in[11];
    const float* b3  = (const float*)d_in[12];
    float* out = (float*)d_out;

    (void)in_sizes; (void)n_in; (void)out_size;

    cudaFuncSetAttribute(k_knn, cudaFuncAttributeMaxDynamicSharedMemorySize,
                         NPTS*(int)sizeof(float4));
    cudaFuncSetAttribute(k_l3, cudaFuncAttributeMaxDynamicSharedMemorySize,
                         (128*65 + 128*32)*(int)sizeof(float));

    float *py1a, *py1b, *py2;
    cudaGetSymbolAddress((void**)&py1a, g_y1a);
    cudaGetSymbolAddress((void**)&py1b, g_y1b);
    cudaGetSymbolAddress((void**)&py2,  g_y2);

    k_zero<<<1, 512>>>();
    k_prep<<<(ROWS2 + 255)/256, 256>>>(pts);
    k_knn<<<BB*(NPTS/64), 1024, NPTS*(int)sizeof(float4)>>>();

    k_l1a<<<ROWS1/256, 256>>>(W1a);
    k_colsum<<<dim3(16, 16), 256>>>(py1a, ROWS1, 0);
    k_fin<<<1, 64>>>(0, 1.0f/(float)ROWS1, 16, g1a, b1a);

    k_l1b<<<ROWS1/256, 256>>>(W1b);
    k_colsum<<<dim3(64, 16), 256>>>(py1b, ROWS1, 128);
    k_fin<<<1, 64>>>(128, 1.0f/(float)ROWS1, 64, g1b, b1b);

    k_pts<<<ROWS2/256, 256>>>(W2);
    k_colsum<<<dim3(64, 4), 256>>>(py2, ROWS2, 256);
    k_fin<<<1, 64>>>(256, 1.0f/(float)ROWS2, 64, g2, b2);

    k_pool<<<dim3(ROWS2/256, 64), 256>>>();

    k_l3<<<ROWS2/32, 256, (128*65 + 128*32)*(int)sizeof(float)>>>(W3);
    k_fin<<<1, 64>>>(384, 1.0f/(float)ROWS2, 64, g3, b3);

    k_out<<<ROWS2/32, 256>>>(out);
}